// round 8
// baseline (speedup 1.0000x reference)
#include <cuda_runtime.h>
#include <cuda_fp16.h>

#define NN 100000
#define EE 1600000
#define IC 128
#define HH 64

// ---------------- device scratch (no allocs allowed) ----------------
__device__ __align__(16) int    g_is64;
__device__ __align__(16) int    g_src32[EE];
__device__ __align__(16) int    g_dst32[EE];
__device__ __align__(16) int    g_deg[NN];
__device__ __align__(16) float  g_dis[NN];
__device__ __align__(16) int    g_ptmp[NN];
__device__ __align__(16) int    g_bsum[512];
__device__ __align__(16) int    g_boff[512];
__device__ __align__(16) int    g_rowptr[NN + 1];
__device__ __align__(16) int    g_cursor[NN];
__device__ __align__(16) int4   g_csr[EE];       // {src, norm(fp32 bits), eid, 0}
__device__ __align__(16) __half g_h0h[NN * HH];  // x @ W1 (fp16)
__device__ __align__(16) float  g_t1[NN * HH];   // relu(agg1 + b1)
__device__ __align__(16) __half g_h1h[NN * HH];  // t1 @ W2 (fp16)
__device__ __align__(16) float  g_hf[NN * HH];   // agg2 + b2
__device__ __align__(16) __half g_ph[NN * HH];   // hf @ Wc1[0:64] + bc1 (fp16)
__device__ __align__(16) __half g_qh[NN * HH];   // hf @ Wc1[64:128]   (fp16)

// ---------------- detect index width + zero degrees (fused) ----------------
__global__ void k_detect_zero(const unsigned* __restrict__ w, int n) {
    int i = blockIdx.x * blockDim.x + threadIdx.x;
    if (i < n) g_deg[i] = 0;
    if (blockIdx.x == 0 && threadIdx.x < 32) {
        int lane = threadIdx.x;
        unsigned acc = 0;
        for (int j = 0; j < 32; j++) acc |= w[(lane * 32 + j) * 2 + 1];
        unsigned any = __ballot_sync(0xffffffffu, acc != 0);
        if (lane == 0) g_is64 = (any == 0u) ? 1 : 0;
    }
}

__global__ void k_convert(const void* __restrict__ ei, int E) {
    int e = blockIdx.x * blockDim.x + threadIdx.x;
    if (e >= 2 * E) return;
    int v;
    if (g_is64) v = (int)((const long long*)ei)[e];
    else        v = ((const int*)ei)[e];
    if (e < E) g_src32[e] = v;
    else { g_dst32[e - E] = v; atomicAdd(&g_deg[v], 1); }
}

// ---------------- scan1 (+ fused dis) ----------------
__global__ void k_scan1(int n) {
    __shared__ int sh[256];
    int i = blockIdx.x * 256 + threadIdx.x;
    int v = (i < n) ? g_deg[i] : 0;
    if (i < n) g_dis[i] = rsqrtf((float)(v + 1));
    sh[threadIdx.x] = v;
    __syncthreads();
    int acc = v;
#pragma unroll
    for (int o = 1; o < 256; o <<= 1) {
        int t = (threadIdx.x >= o) ? sh[threadIdx.x - o] : 0;
        __syncthreads();
        acc += t; sh[threadIdx.x] = acc;
        __syncthreads();
    }
    if (i < n) g_ptmp[i] = acc - v;
    if (threadIdx.x == 255) g_bsum[blockIdx.x] = acc;
}

__global__ void k_scan2(int nb) {
    __shared__ int sh[512];
    int t = threadIdx.x;
    int v = (t < nb) ? g_bsum[t] : 0;
    sh[t] = v;
    __syncthreads();
    int acc = v;
#pragma unroll
    for (int o = 1; o < 512; o <<= 1) {
        int x = (t >= o) ? sh[t - o] : 0;
        __syncthreads();
        acc += x; sh[t] = acc;
        __syncthreads();
    }
    if (t < nb) g_boff[t] = acc - v;
}

__global__ void k_scan3(int n, int E) {
    int i = blockIdx.x * 256 + threadIdx.x;
    if (i < n) {
        int r = g_ptmp[i] + g_boff[blockIdx.x];
        g_rowptr[i] = r;
        g_cursor[i] = r;
    }
    if (i == 0) g_rowptr[n] = E;
}

// ---------------- CSR fill: one STG.128 per edge ----------------
__global__ void k_fill(int E) {
    int e = blockIdx.x * 256 + threadIdx.x;
    if (e >= E) return;
    int s = g_src32[e];
    int d = g_dst32[e];
    int pos = atomicAdd(&g_cursor[d], 1);
    int4 v;
    v.x = s;
    v.y = __float_as_int(g_dis[s] * g_dis[d]);
    v.z = e;
    v.w = 0;
    g_csr[pos] = v;
}

// ---------------- GEMM1: h0 = x @ W1 -> fp16 ----------------
__global__ __launch_bounds__(256) void k_gemm1(const float* __restrict__ x,
                                               const float* __restrict__ W1, int n) {
    __shared__ float Ws[IC * HH];
    __shared__ float xs[8][4 * IC];
    int tid = threadIdx.x;
    for (int i = tid; i < IC * HH / 4; i += 256)
        ((float4*)Ws)[i] = ((const float4*)W1)[i];
    __syncthreads();
    int w = tid >> 5, lane = tid & 31;
    int r0 = blockIdx.x * 32 + w * 4;
    if (r0 >= n) return;
    int nr = min(4, n - r0);
    const float4* xsrc = (const float4*)(x + (size_t)r0 * IC);
    float4* xd = (float4*)xs[w];
    for (int i = lane; i < nr * (IC / 4); i += 32) xd[i] = xsrc[i];
    __syncwarp();
    float acc[4][2] = {};
#pragma unroll 8
    for (int k = 0; k < IC; k++) {
        float w0 = Ws[k * HH + lane], w1 = Ws[k * HH + lane + 32];
#pragma unroll
        for (int rr = 0; rr < 4; rr++) {
            float xv = xs[w][rr * IC + k];
            acc[rr][0] = fmaf(xv, w0, acc[rr][0]);
            acc[rr][1] = fmaf(xv, w1, acc[rr][1]);
        }
    }
    for (int rr = 0; rr < nr; rr++) {
        int r = r0 + rr;
        g_h0h[r * HH + lane]      = __float2half(acc[rr][0]);
        g_h0h[r * HH + lane + 32] = __float2half(acc[rr][1]);
    }
}

// ---------------- CSR gather on fp16 rows (half2 lanes, 4-edge unroll) ----------------
template<int LAYER>
__global__ __launch_bounds__(256) void k_gather(const float* __restrict__ bias, int n) {
    int w = threadIdx.x >> 5, lane = threadIdx.x & 31;
    int node = blockIdx.x * 8 + w;
    if (node >= n) return;
    const __half2* h = (const __half2*)(LAYER ? g_h1h : g_h0h);
    float dd = g_dis[node];
    float d2 = dd * dd;
    float2 self = __half22float2(h[node * 32 + lane]);
    float ax = self.x * d2, ay = self.y * d2;
    int i = g_rowptr[node], end = g_rowptr[node + 1];
    for (; i + 4 <= end; i += 4) {
        int4 e0 = g_csr[i],     e1 = g_csr[i + 1];
        int4 e2 = g_csr[i + 2], e3 = g_csr[i + 3];
        float n0 = __int_as_float(e0.y), n1 = __int_as_float(e1.y);
        float n2 = __int_as_float(e2.y), n3 = __int_as_float(e3.y);
        float2 v0 = __half22float2(h[e0.x * 32 + lane]);
        float2 v1 = __half22float2(h[e1.x * 32 + lane]);
        float2 v2 = __half22float2(h[e2.x * 32 + lane]);
        float2 v3 = __half22float2(h[e3.x * 32 + lane]);
        ax = fmaf(v0.x, n0, ax); ay = fmaf(v0.y, n0, ay);
        ax = fmaf(v1.x, n1, ax); ay = fmaf(v1.y, n1, ay);
        ax = fmaf(v2.x, n2, ax); ay = fmaf(v2.y, n2, ay);
        ax = fmaf(v3.x, n3, ax); ay = fmaf(v3.y, n3, ay);
    }
    for (; i < end; i++) {
        int4 e0 = g_csr[i];
        float n0 = __int_as_float(e0.y);
        float2 v0 = __half22float2(h[e0.x * 32 + lane]);
        ax = fmaf(v0.x, n0, ax); ay = fmaf(v0.y, n0, ay);
    }
    float2 bb = __ldg((const float2*)bias + lane);
    float2 r;
    if (LAYER == 0) {
        r.x = fmaxf(ax + bb.x, 0.f);
        r.y = fmaxf(ay + bb.y, 0.f);
        ((float2*)g_t1)[node * 32 + lane] = r;
    } else {
        r.x = ax + bb.x;
        r.y = ay + bb.y;
        ((float2*)g_hf)[node * 32 + lane] = r;
    }
}

// ---------------- GEMM2: h1 = t1 @ W2 -> fp16 ----------------
__global__ __launch_bounds__(256) void k_gemm2(const float* __restrict__ W2, int n) {
    __shared__ float Ws[HH * HH];
    __shared__ float ts[8][4 * HH];
    int tid = threadIdx.x;
    for (int i = tid; i < HH * HH / 4; i += 256)
        ((float4*)Ws)[i] = ((const float4*)W2)[i];
    __syncthreads();
    int w = tid >> 5, lane = tid & 31;
    int r0 = blockIdx.x * 32 + w * 4;
    if (r0 >= n) return;
    int nr = min(4, n - r0);
    const float4* tsrc = (const float4*)(g_t1 + (size_t)r0 * HH);
    float4* td = (float4*)ts[w];
    for (int i = lane; i < nr * (HH / 4); i += 32) td[i] = tsrc[i];
    __syncwarp();
    float acc[4][2] = {};
#pragma unroll 8
    for (int k = 0; k < HH; k++) {
        float w0 = Ws[k * HH + lane], w1 = Ws[k * HH + lane + 32];
#pragma unroll
        for (int rr = 0; rr < 4; rr++) {
            float tv = ts[w][rr * HH + k];
            acc[rr][0] = fmaf(tv, w0, acc[rr][0]);
            acc[rr][1] = fmaf(tv, w1, acc[rr][1]);
        }
    }
    for (int rr = 0; rr < nr; rr++) {
        int r = r0 + rr;
        g_h1h[r * HH + lane]      = __float2half(acc[rr][0]);
        g_h1h[r * HH + lane + 32] = __float2half(acc[rr][1]);
    }
}

// ---------------- p/q projection -> fp16, bc1 folded into p ----------------
__global__ __launch_bounds__(256) void k_pq(const float* __restrict__ Wc1,
                                            const float* __restrict__ bc1, int n) {
    __shared__ float Ws[2 * HH * HH];
    __shared__ float hs[8][4 * HH];
    int tid = threadIdx.x;
    for (int i = tid; i < 2 * HH * HH / 4; i += 256)
        ((float4*)Ws)[i] = ((const float4*)Wc1)[i];
    __syncthreads();
    int w = tid >> 5, lane = tid & 31;
    int r0 = blockIdx.x * 32 + w * 4;
    if (r0 >= n) return;
    int nr = min(4, n - r0);
    const float4* hsrc = (const float4*)(g_hf + (size_t)r0 * HH);
    float4* hd = (float4*)hs[w];
    for (int i = lane; i < nr * (HH / 4); i += 32) hd[i] = hsrc[i];
    __syncwarp();
    float ap[4][2] = {}, aq[4][2] = {};
#pragma unroll 4
    for (int k = 0; k < HH; k++) {
        float wp0 = Ws[k * HH + lane],        wp1 = Ws[k * HH + lane + 32];
        float wq0 = Ws[(HH + k) * HH + lane], wq1 = Ws[(HH + k) * HH + lane + 32];
#pragma unroll
        for (int rr = 0; rr < 4; rr++) {
            float hv = hs[w][rr * HH + k];
            ap[rr][0] = fmaf(hv, wp0, ap[rr][0]);
            ap[rr][1] = fmaf(hv, wp1, ap[rr][1]);
            aq[rr][0] = fmaf(hv, wq0, aq[rr][0]);
            aq[rr][1] = fmaf(hv, wq1, aq[rr][1]);
        }
    }
    float c0 = __ldg(&bc1[lane]), c1 = __ldg(&bc1[lane + 32]);
    for (int rr = 0; rr < nr; rr++) {
        int r = r0 + rr;
        g_ph[r * HH + lane]      = __float2half(ap[rr][0] + c0);
        g_ph[r * HH + lane + 32] = __float2half(ap[rr][1] + c1);
        g_qh[r * HH + lane]      = __float2half(aq[rr][0]);
        g_qh[r * HH + lane + 32] = __float2half(aq[rr][1]);
    }
}

// ---------------- edge classifier over dst-CSR ----------------
// warp = 1 dst node. q[dst] kept in regs (each lane-in-group holds its 16B
// chunk). 4 groups x 8 lanes process 4 edges/iter: one LDG.128 loads the
// full fp16 p-row per edge. out[eid] scattered by group leader.
__global__ __launch_bounds__(256) void k_cls(const float* __restrict__ Wc2,
                                             const float* __restrict__ bc2,
                                             float2* __restrict__ out, int n) {
    int w = threadIdx.x >> 5, lane = threadIdx.x & 31;
    int node = blockIdx.x * 8 + w;
    if (node >= n) return;
    int grp = lane >> 3, l = lane & 7;
    // q chunk for dims [l*8, l*8+8)
    uint4 qv = *(const uint4*)(g_qh + (size_t)node * HH + l * 8);
    const __half2* qq = (const __half2*)&qv;
    float2 qf[4];
#pragma unroll
    for (int j = 0; j < 4; j++) qf[j] = __half22float2(qq[j]);
    // Wc2 rows for this lane's 8 dims (8 x float2)
    float2 wv[8];
#pragma unroll
    for (int j = 0; j < 8; j++) wv[j] = __ldg((const float2*)Wc2 + l * 8 + j);
    float o0 = __ldg(&bc2[0]), o1 = __ldg(&bc2[1]);

    int beg = g_rowptr[node], end = g_rowptr[node + 1];
    for (int i = beg + grp; i < end; i += 4) {
        int4 ed = g_csr[i];
        int s = ed.x, eid = ed.z;
        uint4 pv = *(const uint4*)(g_ph + (size_t)s * HH + l * 8);
        const __half2* pp = (const __half2*)&pv;
        float s0 = 0.f, s1 = 0.f;
#pragma unroll
        for (int j = 0; j < 4; j++) {
            float2 a = __half22float2(pp[j]);
            float u0 = fmaxf(a.x + qf[j].x, 0.f);
            float u1 = fmaxf(a.y + qf[j].y, 0.f);
            s0 += u0 * wv[2 * j].x + u1 * wv[2 * j + 1].x;
            s1 += u0 * wv[2 * j].y + u1 * wv[2 * j + 1].y;
        }
#pragma unroll
        for (int o = 4; o > 0; o >>= 1) {
            s0 += __shfl_down_sync(0xffffffffu, s0, o, 8);
            s1 += __shfl_down_sync(0xffffffffu, s1, o, 8);
        }
        if (l == 0) {
            float2 r; r.x = s0 + o0; r.y = s1 + o1;
            out[eid] = r;
        }
    }
}

// ---------------- launch ----------------
extern "C" void kernel_launch(void* const* d_in, const int* in_sizes, int n_in,
                              void* d_out, int out_size) {
    const float* x   = (const float*)d_in[0];
    const void*  ei  = d_in[1];
    const float* W1  = (const float*)d_in[2];
    const float* b1  = (const float*)d_in[3];
    const float* W2  = (const float*)d_in[4];
    const float* b2  = (const float*)d_in[5];
    const float* Wc1 = (const float*)d_in[6];
    const float* bc1 = (const float*)d_in[7];
    const float* Wc2 = (const float*)d_in[8];
    const float* bc2 = (const float*)d_in[9];

    int N = in_sizes[0] / IC;   // 100000
    int E = in_sizes[1] / 2;    // 1600000
    int nb = (N + 255) / 256;

    k_detect_zero<<<nb, 256>>>((const unsigned*)ei, N);
    k_convert<<<(2 * E + 255) / 256, 256>>>(ei, E);
    k_scan1<<<nb, 256>>>(N);
    k_scan2<<<1, 512>>>(nb);
    k_scan3<<<nb, 256>>>(N, E);
    k_fill<<<(E + 255) / 256, 256>>>(E);

    k_gemm1<<<(N + 31) / 32, 256>>>(x, W1, N);
    k_gather<0><<<(N + 7) / 8, 256>>>(b1, N);
    k_gemm2<<<(N + 31) / 32, 256>>>(W2, N);
    k_gather<1><<<(N + 7) / 8, 256>>>(b2, N);
    k_pq<<<(N + 31) / 32, 256>>>(Wc1, bc1, N);
    k_cls<<<(N + 7) / 8, 256>>>(Wc2, bc2, (float2*)d_out, N);
}

// round 9
// speedup vs baseline: 1.1570x; 1.1570x over previous
#include <cuda_runtime.h>
#include <cuda_fp16.h>

#define NN 100000
#define EE 1600000
#define IC 128
#define HH 64

// ---------------- device scratch (no allocs allowed) ----------------
__device__ __align__(16) int    g_is64;
__device__ __align__(16) int    g_src32[EE];
__device__ __align__(16) int    g_dst32[EE];
__device__ __align__(16) int    g_deg[NN];
__device__ __align__(16) float  g_dis[NN];
__device__ __align__(16) int    g_ptmp[NN];
__device__ __align__(16) int    g_bsum[512];
__device__ __align__(16) int    g_boff[512];
__device__ __align__(16) int    g_rowptr[NN + 1];
__device__ __align__(16) int    g_cursor[NN];
__device__ __align__(16) int2   g_csre[EE];      // {src, norm (fp32 bits)}
__device__ __align__(16) __half g_h0h[NN * HH];  // x @ W1 (fp16)
__device__ __align__(16) float  g_t1[NN * HH];   // relu(agg1 + b1)
__device__ __align__(16) __half g_h1h[NN * HH];  // t1 @ W2 (fp16)
__device__ __align__(16) float  g_hf[NN * HH];   // agg2 + b2
__device__ __align__(16) __half g_ph[NN * HH];   // hf @ Wc1[0:64] + bc1 (fp16)
__device__ __align__(16) __half g_qh[NN * HH];   // hf @ Wc1[64:128]   (fp16)

// ---------------- detect index width + zero degrees (fused) ----------------
__global__ void k_detect_zero(const unsigned* __restrict__ w, int n) {
    int i = blockIdx.x * blockDim.x + threadIdx.x;
    if (i < n) g_deg[i] = 0;
    if (blockIdx.x == 0 && threadIdx.x < 32) {
        int lane = threadIdx.x;
        unsigned acc = 0;
        for (int j = 0; j < 32; j++) acc |= w[(lane * 32 + j) * 2 + 1];
        unsigned any = __ballot_sync(0xffffffffu, acc != 0);
        if (lane == 0) g_is64 = (any == 0u) ? 1 : 0;
    }
}

__global__ void k_convert(const void* __restrict__ ei, int E) {
    int e = blockIdx.x * blockDim.x + threadIdx.x;
    if (e >= 2 * E) return;
    int v;
    if (g_is64) v = (int)((const long long*)ei)[e];
    else        v = ((const int*)ei)[e];
    if (e < E) g_src32[e] = v;
    else { g_dst32[e - E] = v; atomicAdd(&g_deg[v], 1); }
}

// ---------------- scan1 (+ fused dis) ----------------
__global__ void k_scan1(int n) {
    __shared__ int sh[256];
    int i = blockIdx.x * 256 + threadIdx.x;
    int v = (i < n) ? g_deg[i] : 0;
    if (i < n) g_dis[i] = rsqrtf((float)(v + 1));
    sh[threadIdx.x] = v;
    __syncthreads();
    int acc = v;
#pragma unroll
    for (int o = 1; o < 256; o <<= 1) {
        int t = (threadIdx.x >= o) ? sh[threadIdx.x - o] : 0;
        __syncthreads();
        acc += t; sh[threadIdx.x] = acc;
        __syncthreads();
    }
    if (i < n) g_ptmp[i] = acc - v;
    if (threadIdx.x == 255) g_bsum[blockIdx.x] = acc;
}

__global__ void k_scan2(int nb) {
    __shared__ int sh[512];
    int t = threadIdx.x;
    int v = (t < nb) ? g_bsum[t] : 0;
    sh[t] = v;
    __syncthreads();
    int acc = v;
#pragma unroll
    for (int o = 1; o < 512; o <<= 1) {
        int x = (t >= o) ? sh[t - o] : 0;
        __syncthreads();
        acc += x; sh[t] = acc;
        __syncthreads();
    }
    if (t < nb) g_boff[t] = acc - v;
}

__global__ void k_scan3(int n, int E) {
    int i = blockIdx.x * 256 + threadIdx.x;
    if (i < n) {
        int r = g_ptmp[i] + g_boff[blockIdx.x];
        g_rowptr[i] = r;
        g_cursor[i] = r;
    }
    if (i == 0) g_rowptr[n] = E;
}

// ---------------- CSR fill: one STG.64 per edge ----------------
__global__ void k_fill(int E) {
    int e = blockIdx.x * 256 + threadIdx.x;
    if (e >= E) return;
    int s = g_src32[e];
    int d = g_dst32[e];
    int pos = atomicAdd(&g_cursor[d], 1);
    int2 v;
    v.x = s;
    v.y = __float_as_int(g_dis[s] * g_dis[d]);
    g_csre[pos] = v;
}

// ---------------- GEMM1: h0 = x @ W1 -> fp16 ----------------
__global__ __launch_bounds__(256) void k_gemm1(const float* __restrict__ x,
                                               const float* __restrict__ W1, int n) {
    __shared__ float Ws[IC * HH];
    __shared__ float xs[8][4 * IC];
    int tid = threadIdx.x;
    for (int i = tid; i < IC * HH / 4; i += 256)
        ((float4*)Ws)[i] = ((const float4*)W1)[i];
    __syncthreads();
    int w = tid >> 5, lane = tid & 31;
    int r0 = blockIdx.x * 32 + w * 4;
    if (r0 >= n) return;
    int nr = min(4, n - r0);
    const float4* xsrc = (const float4*)(x + (size_t)r0 * IC);
    float4* xd = (float4*)xs[w];
    for (int i = lane; i < nr * (IC / 4); i += 32) xd[i] = xsrc[i];
    __syncwarp();
    float acc[4][2] = {};
#pragma unroll 8
    for (int k = 0; k < IC; k++) {
        float w0 = Ws[k * HH + lane], w1 = Ws[k * HH + lane + 32];
#pragma unroll
        for (int rr = 0; rr < 4; rr++) {
            float xv = xs[w][rr * IC + k];
            acc[rr][0] = fmaf(xv, w0, acc[rr][0]);
            acc[rr][1] = fmaf(xv, w1, acc[rr][1]);
        }
    }
    for (int rr = 0; rr < nr; rr++) {
        int r = r0 + rr;
        g_h0h[r * HH + lane]      = __float2half(acc[rr][0]);
        g_h0h[r * HH + lane + 32] = __float2half(acc[rr][1]);
    }
}

// ---------------- CSR gather on fp16 rows (half2 lanes, 4-edge unroll) ----------------
template<int LAYER>
__global__ __launch_bounds__(256) void k_gather(const float* __restrict__ bias, int n) {
    int w = threadIdx.x >> 5, lane = threadIdx.x & 31;
    int node = blockIdx.x * 8 + w;
    if (node >= n) return;
    const __half2* h = (const __half2*)(LAYER ? g_h1h : g_h0h);
    float dd = g_dis[node];
    float d2 = dd * dd;
    float2 self = __half22float2(h[node * 32 + lane]);
    float ax = self.x * d2, ay = self.y * d2;
    int i = g_rowptr[node], end = g_rowptr[node + 1];
    for (; i + 4 <= end; i += 4) {
        int2 e0 = g_csre[i],     e1 = g_csre[i + 1];
        int2 e2 = g_csre[i + 2], e3 = g_csre[i + 3];
        float n0 = __int_as_float(e0.y), n1 = __int_as_float(e1.y);
        float n2 = __int_as_float(e2.y), n3 = __int_as_float(e3.y);
        float2 v0 = __half22float2(h[e0.x * 32 + lane]);
        float2 v1 = __half22float2(h[e1.x * 32 + lane]);
        float2 v2 = __half22float2(h[e2.x * 32 + lane]);
        float2 v3 = __half22float2(h[e3.x * 32 + lane]);
        ax = fmaf(v0.x, n0, ax); ay = fmaf(v0.y, n0, ay);
        ax = fmaf(v1.x, n1, ax); ay = fmaf(v1.y, n1, ay);
        ax = fmaf(v2.x, n2, ax); ay = fmaf(v2.y, n2, ay);
        ax = fmaf(v3.x, n3, ax); ay = fmaf(v3.y, n3, ay);
    }
    for (; i < end; i++) {
        int2 e0 = g_csre[i];
        float n0 = __int_as_float(e0.y);
        float2 v0 = __half22float2(h[e0.x * 32 + lane]);
        ax = fmaf(v0.x, n0, ax); ay = fmaf(v0.y, n0, ay);
    }
    float2 bb = __ldg((const float2*)bias + lane);
    float2 r;
    if (LAYER == 0) {
        r.x = fmaxf(ax + bb.x, 0.f);
        r.y = fmaxf(ay + bb.y, 0.f);
        ((float2*)g_t1)[node * 32 + lane] = r;
    } else {
        r.x = ax + bb.x;
        r.y = ay + bb.y;
        ((float2*)g_hf)[node * 32 + lane] = r;
    }
}

// ---------------- GEMM2: h1 = t1 @ W2 -> fp16 ----------------
__global__ __launch_bounds__(256) void k_gemm2(const float* __restrict__ W2, int n) {
    __shared__ float Ws[HH * HH];
    __shared__ float ts[8][4 * HH];
    int tid = threadIdx.x;
    for (int i = tid; i < HH * HH / 4; i += 256)
        ((float4*)Ws)[i] = ((const float4*)W2)[i];
    __syncthreads();
    int w = tid >> 5, lane = tid & 31;
    int r0 = blockIdx.x * 32 + w * 4;
    if (r0 >= n) return;
    int nr = min(4, n - r0);
    const float4* tsrc = (const float4*)(g_t1 + (size_t)r0 * HH);
    float4* td = (float4*)ts[w];
    for (int i = lane; i < nr * (HH / 4); i += 32) td[i] = tsrc[i];
    __syncwarp();
    float acc[4][2] = {};
#pragma unroll 8
    for (int k = 0; k < HH; k++) {
        float w0 = Ws[k * HH + lane], w1 = Ws[k * HH + lane + 32];
#pragma unroll
        for (int rr = 0; rr < 4; rr++) {
            float tv = ts[w][rr * HH + k];
            acc[rr][0] = fmaf(tv, w0, acc[rr][0]);
            acc[rr][1] = fmaf(tv, w1, acc[rr][1]);
        }
    }
    for (int rr = 0; rr < nr; rr++) {
        int r = r0 + rr;
        g_h1h[r * HH + lane]      = __float2half(acc[rr][0]);
        g_h1h[r * HH + lane + 32] = __float2half(acc[rr][1]);
    }
}

// ---------------- p/q projection -> fp16, bc1 folded into p ----------------
__global__ __launch_bounds__(256) void k_pq(const float* __restrict__ Wc1,
                                            const float* __restrict__ bc1, int n) {
    __shared__ float Ws[2 * HH * HH];
    __shared__ float hs[8][4 * HH];
    int tid = threadIdx.x;
    for (int i = tid; i < 2 * HH * HH / 4; i += 256)
        ((float4*)Ws)[i] = ((const float4*)Wc1)[i];
    __syncthreads();
    int w = tid >> 5, lane = tid & 31;
    int r0 = blockIdx.x * 32 + w * 4;
    if (r0 >= n) return;
    int nr = min(4, n - r0);
    const float4* hsrc = (const float4*)(g_hf + (size_t)r0 * HH);
    float4* hd = (float4*)hs[w];
    for (int i = lane; i < nr * (HH / 4); i += 32) hd[i] = hsrc[i];
    __syncwarp();
    float ap[4][2] = {}, aq[4][2] = {};
#pragma unroll 4
    for (int k = 0; k < HH; k++) {
        float wp0 = Ws[k * HH + lane],        wp1 = Ws[k * HH + lane + 32];
        float wq0 = Ws[(HH + k) * HH + lane], wq1 = Ws[(HH + k) * HH + lane + 32];
#pragma unroll
        for (int rr = 0; rr < 4; rr++) {
            float hv = hs[w][rr * HH + k];
            ap[rr][0] = fmaf(hv, wp0, ap[rr][0]);
            ap[rr][1] = fmaf(hv, wp1, ap[rr][1]);
            aq[rr][0] = fmaf(hv, wq0, aq[rr][0]);
            aq[rr][1] = fmaf(hv, wq1, aq[rr][1]);
        }
    }
    float c0 = __ldg(&bc1[lane]), c1 = __ldg(&bc1[lane + 32]);
    for (int rr = 0; rr < nr; rr++) {
        int r = r0 + rr;
        g_ph[r * HH + lane]      = __float2half(ap[rr][0] + c0);
        g_ph[r * HH + lane + 32] = __float2half(ap[rr][1] + c1);
        g_qh[r * HH + lane]      = __float2half(aq[rr][0]);
        g_qh[r * HH + lane + 32] = __float2half(aq[rr][1]);
    }
}

// ---------------- edge classifier: 8 lanes/edge, LDG.128 fp16 rows ----------------
__global__ __launch_bounds__(256) void k_cls(const float* __restrict__ Wc2,
                                             const float* __restrict__ bc2,
                                             float2* __restrict__ out, int E) {
    int t = blockIdx.x * 256 + threadIdx.x;
    int e = t >> 3;
    if (e >= E) return;
    int l = t & 7;
    int s = g_src32[e];
    int d = g_dst32[e];
    uint4 pv = *(const uint4*)(g_ph + (size_t)s * HH + l * 8);
    uint4 qv = *(const uint4*)(g_qh + (size_t)d * HH + l * 8);
    const __half2* pp = (const __half2*)&pv;
    const __half2* qq = (const __half2*)&qv;
    float s0 = 0.f, s1 = 0.f;
#pragma unroll
    for (int j = 0; j < 4; j++) {
        float2 a = __half22float2(pp[j]);
        float2 b = __half22float2(qq[j]);
        float u0 = fmaxf(a.x + b.x, 0.f);
        float u1 = fmaxf(a.y + b.y, 0.f);
        int c = l * 8 + j * 2;
        float2 wA = __ldg((const float2*)Wc2 + c);
        float2 wB = __ldg((const float2*)Wc2 + c + 1);
        s0 += u0 * wA.x + u1 * wB.x;
        s1 += u0 * wA.y + u1 * wB.y;
    }
#pragma unroll
    for (int o = 4; o > 0; o >>= 1) {
        s0 += __shfl_down_sync(0xffffffffu, s0, o, 8);
        s1 += __shfl_down_sync(0xffffffffu, s1, o, 8);
    }
    if (l == 0) {
        float2 r;
        r.x = s0 + __ldg(&bc2[0]);
        r.y = s1 + __ldg(&bc2[1]);
        out[e] = r;
    }
}

// ---------------- launch ----------------
extern "C" void kernel_launch(void* const* d_in, const int* in_sizes, int n_in,
                              void* d_out, int out_size) {
    const float* x   = (const float*)d_in[0];
    const void*  ei  = d_in[1];
    const float* W1  = (const float*)d_in[2];
    const float* b1  = (const float*)d_in[3];
    const float* W2  = (const float*)d_in[4];
    const float* b2  = (const float*)d_in[5];
    const float* Wc1 = (const float*)d_in[6];
    const float* bc1 = (const float*)d_in[7];
    const float* Wc2 = (const float*)d_in[8];
    const float* bc2 = (const float*)d_in[9];

    int N = in_sizes[0] / IC;   // 100000
    int E = in_sizes[1] / 2;    // 1600000
    int nb = (N + 255) / 256;

    k_detect_zero<<<nb, 256>>>((const unsigned*)ei, N);
    k_convert<<<(2 * E + 255) / 256, 256>>>(ei, E);
    k_scan1<<<nb, 256>>>(N);
    k_scan2<<<1, 512>>>(nb);
    k_scan3<<<nb, 256>>>(N, E);
    k_fill<<<(E + 255) / 256, 256>>>(E);

    k_gemm1<<<(N + 31) / 32, 256>>>(x, W1, N);
    k_gather<0><<<(N + 7) / 8, 256>>>(b1, N);
    k_gemm2<<<(N + 31) / 32, 256>>>(W2, N);
    k_gather<1><<<(N + 7) / 8, 256>>>(b2, N);
    k_pq<<<(N + 31) / 32, 256>>>(Wc1, bc1, N);
    k_cls<<<(int)(((long long)E * 8 + 255) / 256), 256>>>(Wc2, bc2, (float2*)d_out, E);
}